// round 1
// baseline (speedup 1.0000x reference)
#include <cuda_runtime.h>
#include <math.h>

#define Bn 2
#define Tn 2048
#define Dn 1024
#define Hn 16
#define Gn 4
#define Kn 64
#define Rn (Hn / Gn)
#define Fn 4096
#define EPSF 1e-6f
#define Mrows (Bn * Tn)

// ---------------- scratch (alloc-free rule: __device__ globals) ----------------
__device__ float g_x[Mrows * Dn];        // ln1 output
__device__ float g_q[Mrows * Hn * Kn];   // q proj
__device__ float g_k[Mrows * Gn * Kn];   // k proj
__device__ float g_v[Mrows * Gn * Kn];   // v proj
__device__ float g_attn[Mrows * Hn * Kn];
__device__ float g_h2[Mrows * Dn];       // hidden + attn @ o_w
__device__ float g_y[Mrows * Dn];        // ln2 output
__device__ float g_gate[Mrows * Fn];
__device__ float g_up[Mrows * Fn];

// ---------------- RMSNorm over last dim Dn ----------------
__global__ void rmsnorm_k(const float* __restrict__ in, const float* __restrict__ sc,
                          float* __restrict__ out) {
    int row = blockIdx.x;
    const float* x = in + (size_t)row * Dn;
    float ss = 0.f;
    for (int i = threadIdx.x; i < Dn; i += blockDim.x) {
        float v = x[i];
        ss += v * v;
    }
    for (int o = 16; o; o >>= 1) ss += __shfl_xor_sync(0xFFFFFFFFu, ss, o);
    __shared__ float sm[8];
    int w = threadIdx.x >> 5;
    if ((threadIdx.x & 31) == 0) sm[w] = ss;
    __syncthreads();
    if (threadIdx.x == 0) {
        float tot = 0.f;
        for (int i = 0; i < 8; i++) tot += sm[i];
        sm[0] = tot;
    }
    __syncthreads();
    float inv = rsqrtf(sm[0] / (float)Dn + EPSF);
    float* o = out + (size_t)row * Dn;
    for (int i = threadIdx.x; i < Dn; i += blockDim.x) o[i] = x[i] * inv * sc[i];
}

// ---------------- per-head RMSNorm (K=64) + RoPE, warp per (b,t,head) ----------------
__global__ void norm_rope_k(float* __restrict__ qk, const float* __restrict__ nscale,
                            const float* __restrict__ sinp, const float* __restrict__ cosp,
                            int nheads) {
    int gw = (blockIdx.x * blockDim.x + threadIdx.x) >> 5;
    int lane = threadIdx.x & 31;
    int total = Bn * Tn * nheads;
    if (gw >= total) return;
    int bt = gw / nheads;           // (b*T + t)
    float* p = qk + (size_t)gw * Kn;
    float x1 = p[lane];
    float x2 = p[lane + 32];
    float ss = x1 * x1 + x2 * x2;
    for (int o = 16; o; o >>= 1) ss += __shfl_xor_sync(0xFFFFFFFFu, ss, o);
    float inv = rsqrtf(ss / (float)Kn + EPSF);
    x1 = x1 * inv * nscale[lane];
    x2 = x2 * inv * nscale[lane + 32];
    float s = sinp[bt * (Kn / 2) + lane];
    float c = cosp[bt * (Kn / 2) + lane];
    p[lane]      = x1 * c - x2 * s;
    p[lane + 32] = x2 * c + x1 * s;
}

// ---------------- causal GQA attention, warp per (b,t,h), online softmax ----------------
__global__ void attn_k(const float* __restrict__ q, const float* __restrict__ k,
                       const float* __restrict__ v, float* __restrict__ out) {
    int gw = (blockIdx.x * blockDim.x + threadIdx.x) >> 5;
    int lane = threadIdx.x & 31;
    if (gw >= Bn * Tn * Hn) return;
    int h = gw % Hn;
    int t = (gw / Hn) % Tn;
    int b = gw / (Hn * Tn);
    int g = h / Rn;

    const float* qp = q + (size_t)gw * Kn;
    float q0 = qp[lane], q1 = qp[lane + 32];
    const float scale = 0.125f;  // K^-0.5, K=64

    float m = -INFINITY, l = 0.f, acc0 = 0.f, acc1 = 0.f;
    for (int s = 0; s <= t; s++) {
        const float* kp = k + (size_t)(((b * Tn + s) * Gn + g)) * Kn;
        float d = q0 * kp[lane] + q1 * kp[lane + 32];
        for (int o = 16; o; o >>= 1) d += __shfl_xor_sync(0xFFFFFFFFu, d, o);
        d *= scale;
        float mn = fmaxf(m, d);
        float corr = __expf(m - mn);
        float w = __expf(d - mn);
        const float* vp = v + (size_t)(((b * Tn + s) * Gn + g)) * Kn;
        l = l * corr + w;
        acc0 = acc0 * corr + w * vp[lane];
        acc1 = acc1 * corr + w * vp[lane + 32];
        m = mn;
    }
    float invl = 1.f / l;
    float* op = out + (size_t)gw * Kn;
    op[lane]      = acc0 * invl;
    op[lane + 32] = acc1 * invl;
}

// ---------------- SGEMM: C[M,N] = A[M,Kd] @ W[Kd,N] (+ residual) ----------------
// 128x128 tile, BK=8, 256 threads, 8x8 per-thread micro-tile. All dims divisible.
#define BM 128
#define BN 128
#define BK 8
#define TM 8
#define TN 8

__global__ __launch_bounds__(256) void sgemm_k(const float* __restrict__ A,
                                               const float* __restrict__ W,
                                               const float* __restrict__ res,
                                               float* __restrict__ C,
                                               int M, int N, int Kd) {
    __shared__ float As[BK][BM];
    __shared__ float Ws[BK][BN];

    int bx = blockIdx.x;  // N tile
    int by = blockIdx.y;  // M tile
    int tid = threadIdx.x;
    int tx = tid & 15;    // 16 thread cols
    int ty = tid >> 4;    // 16 thread rows

    const float* Ab = A + (size_t)by * BM * Kd;
    const float* Wb = W + (size_t)bx * BN;

    int arow = tid >> 1;
    int acol = (tid & 1) * 4;
    int wrow = tid >> 5;
    int wcol = (tid & 31) * 4;

    float acc[TM][TN];
#pragma unroll
    for (int i = 0; i < TM; i++)
#pragma unroll
        for (int j = 0; j < TN; j++) acc[i][j] = 0.f;

    for (int k0 = 0; k0 < Kd; k0 += BK) {
        float4 a4 = *(const float4*)(Ab + (size_t)arow * Kd + k0 + acol);
        As[acol + 0][arow] = a4.x;
        As[acol + 1][arow] = a4.y;
        As[acol + 2][arow] = a4.z;
        As[acol + 3][arow] = a4.w;
        float4 w4 = *(const float4*)(Wb + (size_t)(k0 + wrow) * N + wcol);
        *(float4*)&Ws[wrow][wcol] = w4;
        __syncthreads();

#pragma unroll
        for (int kk = 0; kk < BK; kk++) {
            float ra[TM], rb[TN];
#pragma unroll
            for (int i = 0; i < TM; i++) ra[i] = As[kk][ty * TM + i];
#pragma unroll
            for (int j = 0; j < TN; j++) rb[j] = Ws[kk][tx * TN + j];
#pragma unroll
            for (int i = 0; i < TM; i++)
#pragma unroll
                for (int j = 0; j < TN; j++) acc[i][j] += ra[i] * rb[j];
        }
        __syncthreads();
    }

#pragma unroll
    for (int i = 0; i < TM; i++) {
        int row = by * BM + ty * TM + i;
#pragma unroll
        for (int j = 0; j < TN; j += 4) {
            int col = bx * BN + tx * TN + j;
            float4 r = make_float4(acc[i][j], acc[i][j + 1], acc[i][j + 2], acc[i][j + 3]);
            if (res != nullptr) {
                float4 hsum = *(const float4*)(res + (size_t)row * N + col);
                r.x += hsum.x; r.y += hsum.y; r.z += hsum.z; r.w += hsum.w;
            }
            *(float4*)(C + (size_t)row * N + col) = r;
        }
    }
}

// ---------------- silu(gate) * up, in place into gate ----------------
__global__ void silu_mul_k(float* __restrict__ gate, const float* __restrict__ up, int n) {
    int i = blockIdx.x * blockDim.x + threadIdx.x;
    if (i < n) {
        float gv = gate[i];
        float sig = 1.f / (1.f + __expf(-gv));
        gate[i] = gv * sig * up[i];
    }
}

// ---------------- launch ----------------
static void gemm(const float* A, const float* W, const float* res, float* C,
                 int M, int N, int Kd) {
    dim3 grid(N / BN, M / BM);
    sgemm_k<<<grid, 256>>>(A, W, res, C, M, N, Kd);
}

extern "C" void kernel_launch(void* const* d_in, const int* in_sizes, int n_in,
                              void* d_out, int out_size) {
    const float* hidden = (const float*)d_in[0];
    const float* sinp   = (const float*)d_in[1];
    const float* cosp   = (const float*)d_in[2];
    /* d_in[3] = mask (exact causal tril; applied analytically) */
    const float* ln1    = (const float*)d_in[4];
    const float* ln2    = (const float*)d_in[5];
    const float* qn     = (const float*)d_in[6];
    const float* kn     = (const float*)d_in[7];
    const float* q_w    = (const float*)d_in[8];
    const float* k_w    = (const float*)d_in[9];
    const float* v_w    = (const float*)d_in[10];
    const float* o_w    = (const float*)d_in[11];
    const float* gate_w = (const float*)d_in[12];
    const float* up_w   = (const float*)d_in[13];
    const float* down_w = (const float*)d_in[14];
    float* out = (float*)d_out;

    float *x, *q, *k, *v, *attn, *h2, *y, *gate, *up;
    cudaGetSymbolAddress((void**)&x, g_x);
    cudaGetSymbolAddress((void**)&q, g_q);
    cudaGetSymbolAddress((void**)&k, g_k);
    cudaGetSymbolAddress((void**)&v, g_v);
    cudaGetSymbolAddress((void**)&attn, g_attn);
    cudaGetSymbolAddress((void**)&h2, g_h2);
    cudaGetSymbolAddress((void**)&y, g_y);
    cudaGetSymbolAddress((void**)&gate, g_gate);
    cudaGetSymbolAddress((void**)&up, g_up);

    const int M = Mrows;

    // 1. x = rmsnorm(hidden, ln1)
    rmsnorm_k<<<M, 256>>>(hidden, ln1, x);

    // 2. q/k/v projections
    gemm(x, q_w, nullptr, q, M, Hn * Kn, Dn);
    gemm(x, k_w, nullptr, k, M, Gn * Kn, Dn);
    gemm(x, v_w, nullptr, v, M, Gn * Kn, Dn);

    // 3. per-head rmsnorm + rope
    {
        int warps_q = Bn * Tn * Hn;
        norm_rope_k<<<(warps_q * 32) / 256, 256>>>(q, qn, sinp, cosp, Hn);
        int warps_k = Bn * Tn * Gn;
        norm_rope_k<<<(warps_k * 32) / 256, 256>>>(k, kn, sinp, cosp, Gn);
    }

    // 4. causal attention
    {
        int warps = Bn * Tn * Hn;
        attn_k<<<(warps * 32) / 256, 256>>>(q, k, v, attn);
    }

    // 5. h2 = hidden + attn @ o_w
    gemm(attn, o_w, hidden, h2, M, Dn, Hn * Kn);

    // 6. y = rmsnorm(h2, ln2)
    rmsnorm_k<<<M, 256>>>(h2, ln2, y);

    // 7. gate/up projections
    gemm(y, gate_w, nullptr, gate, M, Fn, Dn);
    gemm(y, up_w, nullptr, up, M, Fn, Dn);

    // 8. gate = silu(gate) * up
    {
        int n = M * Fn;
        silu_mul_k<<<(n + 255) / 256, 256>>>(gate, up, n);
    }

    // 9. out = h2 + gate @ down_w
    gemm(gate, down_w, h2, out, M, Dn, Fn);
}

// round 2
// speedup vs baseline: 1.7269x; 1.7269x over previous
#include <cuda_runtime.h>
#include <math.h>
#include <stdint.h>

#define Bn 2
#define Tn 2048
#define Dn 1024
#define Hn 16
#define Gn 4
#define Kn 64
#define Rn (Hn / Gn)
#define Fn 4096
#define EPSF 1e-6f
#define Mrows (Bn * Tn)

// ---------------- scratch (alloc-free rule: __device__ globals) ----------------
__device__ float g_x[Mrows * Dn];
__device__ float g_q[Mrows * Hn * Kn];
__device__ float g_k[Mrows * Gn * Kn];
__device__ float g_v[Mrows * Gn * Kn];
__device__ float g_attn[Mrows * Hn * Kn];
__device__ float g_h2[Mrows * Dn];
__device__ float g_y[Mrows * Dn];
__device__ float g_gate[Mrows * Fn];
__device__ float g_up[Mrows * Fn];

// ---------------- RMSNorm over last dim Dn ----------------
__global__ void rmsnorm_k(const float* __restrict__ in, const float* __restrict__ sc,
                          float* __restrict__ out) {
    int row = blockIdx.x;
    const float* x = in + (size_t)row * Dn;
    float ss = 0.f;
    for (int i = threadIdx.x; i < Dn; i += blockDim.x) {
        float v = x[i];
        ss += v * v;
    }
    for (int o = 16; o; o >>= 1) ss += __shfl_xor_sync(0xFFFFFFFFu, ss, o);
    __shared__ float sm[8];
    int w = threadIdx.x >> 5;
    if ((threadIdx.x & 31) == 0) sm[w] = ss;
    __syncthreads();
    if (threadIdx.x == 0) {
        float tot = 0.f;
        for (int i = 0; i < 8; i++) tot += sm[i];
        sm[0] = tot;
    }
    __syncthreads();
    float inv = rsqrtf(sm[0] / (float)Dn + EPSF);
    float* o = out + (size_t)row * Dn;
    for (int i = threadIdx.x; i < Dn; i += blockDim.x) o[i] = x[i] * inv * sc[i];
}

// ---------------- per-head RMSNorm (K=64) + RoPE ----------------
__global__ void norm_rope_k(float* __restrict__ qk, const float* __restrict__ nscale,
                            const float* __restrict__ sinp, const float* __restrict__ cosp,
                            int nheads) {
    int gw = (blockIdx.x * blockDim.x + threadIdx.x) >> 5;
    int lane = threadIdx.x & 31;
    int total = Bn * Tn * nheads;
    if (gw >= total) return;
    int bt = gw / nheads;
    float* p = qk + (size_t)gw * Kn;
    float x1 = p[lane];
    float x2 = p[lane + 32];
    float ss = x1 * x1 + x2 * x2;
    for (int o = 16; o; o >>= 1) ss += __shfl_xor_sync(0xFFFFFFFFu, ss, o);
    float inv = rsqrtf(ss / (float)Kn + EPSF);
    x1 = x1 * inv * nscale[lane];
    x2 = x2 * inv * nscale[lane + 32];
    float s = sinp[bt * (Kn / 2) + lane];
    float c = cosp[bt * (Kn / 2) + lane];
    p[lane]      = x1 * c - x2 * s;
    p[lane + 32] = x2 * c + x1 * s;
}

// ---------------- causal GQA attention: warp per (b,t,g), 4 heads ----------------
__global__ void attn4_k(const float* __restrict__ q, const float* __restrict__ k,
                        const float* __restrict__ v, float* __restrict__ out) {
    int gw = (blockIdx.x * blockDim.x + threadIdx.x) >> 5;
    int lane = threadIdx.x & 31;
    if (gw >= Bn * Tn * Gn) return;
    int g = gw % Gn;
    int t = (gw / Gn) % Tn;
    int b = gw / (Gn * Tn);

    const float* qp = q + ((size_t)((b * Tn + t) * Hn + g * Rn)) * Kn;
    float q0[4], q1[4];
#pragma unroll
    for (int r = 0; r < 4; r++) {
        q0[r] = qp[r * Kn + lane];
        q1[r] = qp[r * Kn + lane + 32];
    }
    const float scale = 0.125f;
    float m[4], l[4], a0[4], a1[4];
#pragma unroll
    for (int r = 0; r < 4; r++) { m[r] = -INFINITY; l[r] = 0.f; a0[r] = 0.f; a1[r] = 0.f; }

    const float* kbase = k + ((size_t)b * Tn * Gn + g) * Kn;
    const float* vbase = v + ((size_t)b * Tn * Gn + g) * Kn;

    for (int s = 0; s <= t; s++) {
        const float* kp = kbase + (size_t)s * (Gn * Kn);
        float k0v = kp[lane], k1v = kp[lane + 32];
        float d0 = q0[0] * k0v + q1[0] * k1v;
        float d1 = q0[1] * k0v + q1[1] * k1v;
        float d2 = q0[2] * k0v + q1[2] * k1v;
        float d3 = q0[3] * k0v + q1[3] * k1v;
#pragma unroll
        for (int o = 16; o; o >>= 1) {
            d0 += __shfl_xor_sync(0xFFFFFFFFu, d0, o);
            d1 += __shfl_xor_sync(0xFFFFFFFFu, d1, o);
            d2 += __shfl_xor_sync(0xFFFFFFFFu, d2, o);
            d3 += __shfl_xor_sync(0xFFFFFFFFu, d3, o);
        }
        const float* vp = vbase + (size_t)s * (Gn * Kn);
        float v0v = vp[lane], v1v = vp[lane + 32];
        float d[4] = {d0, d1, d2, d3};
#pragma unroll
        for (int r = 0; r < 4; r++) {
            float dr = d[r] * scale;
            float mn = fmaxf(m[r], dr);
            float corr = __expf(m[r] - mn);
            float w = __expf(dr - mn);
            l[r] = l[r] * corr + w;
            a0[r] = a0[r] * corr + w * v0v;
            a1[r] = a1[r] * corr + w * v1v;
            m[r] = mn;
        }
    }
#pragma unroll
    for (int r = 0; r < 4; r++) {
        float* op = out + ((size_t)((b * Tn + t) * Hn + g * Rn + r)) * Kn;
        float invl = 1.f / l[r];
        op[lane]      = a0[r] * invl;
        op[lane + 32] = a1[r] * invl;
    }
}

// ---------------- TF32 tensor-core GEMM ----------------
// C[M,N] = A[M,Kd] @ W[Kd,N] (+res). 128x128x16 block tile, 8 warps (2x4),
// warp tile 64x32 via mma.sync m16n8k8 tf32. Double-buffered smem.
#define GBM 128
#define GBN 128
#define GBK 16
#define SA 20    // As row stride (floats): conflict-free fragment LDS
#define SB 136   // Bs row stride

__device__ __forceinline__ float to_tf32(float x) {
    uint32_t u;
    asm("cvt.rna.tf32.f32 %0, %1;" : "=r"(u) : "f"(x));
    return __uint_as_float(u);
}

__global__ __launch_bounds__(256, 2) void tf32gemm_k(
    const float* __restrict__ A, const float* __restrict__ W,
    const float* __restrict__ res, float* __restrict__ C,
    int M, int N, int Kd) {
    __shared__ float As[2][GBM * SA];
    __shared__ float Bs[2][GBK * SB];

    int tid = threadIdx.x;
    int lane = tid & 31;
    int wid = tid >> 5;
    int wm = wid >> 2;   // 0..1
    int wn = wid & 3;    // 0..3
    int fr = lane >> 2;  // 0..7
    int fc = lane & 3;   // 0..3

    // global load indexing
    int a_row = tid >> 2;        // 0..63 (and +64)
    int a_col = (tid & 3) * 4;   // 0,4,8,12
    int b_row = tid >> 5;        // 0..7 (and +8)
    int b_col = (tid & 31) * 4;  // 0..124

    const float* Aptr = A + (size_t)(blockIdx.y * GBM) * Kd;
    const float* Wptr = W + (size_t)blockIdx.x * GBN;

    float acc[4][4][4];
#pragma unroll
    for (int mi = 0; mi < 4; mi++)
#pragma unroll
        for (int ni = 0; ni < 4; ni++)
#pragma unroll
            for (int c = 0; c < 4; c++) acc[mi][ni][c] = 0.f;

    float4 ra0, ra1, rb0, rb1;

#define LOAD_REGS(k0)                                                        \
    ra0 = *(const float4*)(Aptr + (size_t)a_row * Kd + (k0) + a_col);        \
    ra1 = *(const float4*)(Aptr + (size_t)(a_row + 64) * Kd + (k0) + a_col); \
    rb0 = *(const float4*)(Wptr + (size_t)((k0) + b_row) * N + b_col);       \
    rb1 = *(const float4*)(Wptr + (size_t)((k0) + b_row + 8) * N + b_col);

#define STORE_STAGE(st)                                                           \
    {                                                                             \
        float* pa0 = &As[st][a_row * SA + a_col];                                 \
        pa0[0] = to_tf32(ra0.x); pa0[1] = to_tf32(ra0.y);                         \
        pa0[2] = to_tf32(ra0.z); pa0[3] = to_tf32(ra0.w);                         \
        float* pa1 = &As[st][(a_row + 64) * SA + a_col];                          \
        pa1[0] = to_tf32(ra1.x); pa1[1] = to_tf32(ra1.y);                         \
        pa1[2] = to_tf32(ra1.z); pa1[3] = to_tf32(ra1.w);                         \
        float* pb0 = &Bs[st][b_row * SB + b_col];                                 \
        pb0[0] = to_tf32(rb0.x); pb0[1] = to_tf32(rb0.y);                         \
        pb0[2] = to_tf32(rb0.z); pb0[3] = to_tf32(rb0.w);                         \
        float* pb1 = &Bs[st][(b_row + 8) * SB + b_col];                           \
        pb1[0] = to_tf32(rb1.x); pb1[1] = to_tf32(rb1.y);                         \
        pb1[2] = to_tf32(rb1.z); pb1[3] = to_tf32(rb1.w);                         \
    }

#define COMPUTE_STAGE(st)                                                         \
    {                                                                             \
        _Pragma("unroll")                                                         \
        for (int kk = 0; kk < GBK; kk += 8) {                                     \
            uint32_t af[4][4], bf[4][2];                                          \
            _Pragma("unroll")                                                     \
            for (int mi = 0; mi < 4; mi++) {                                      \
                int r0 = wm * 64 + mi * 16 + fr;                                  \
                af[mi][0] = __float_as_uint(As[st][r0 * SA + kk + fc]);           \
                af[mi][1] = __float_as_uint(As[st][(r0 + 8) * SA + kk + fc]);     \
                af[mi][2] = __float_as_uint(As[st][r0 * SA + kk + fc + 4]);       \
                af[mi][3] = __float_as_uint(As[st][(r0 + 8) * SA + kk + fc + 4]); \
            }                                                                     \
            _Pragma("unroll")                                                     \
            for (int ni = 0; ni < 4; ni++) {                                      \
                int nc = wn * 32 + ni * 8 + fr;                                   \
                bf[ni][0] = __float_as_uint(Bs[st][(kk + fc) * SB + nc]);         \
                bf[ni][1] = __float_as_uint(Bs[st][(kk + fc + 4) * SB + nc]);     \
            }                                                                     \
            _Pragma("unroll")                                                     \
            for (int mi = 0; mi < 4; mi++)                                        \
                _Pragma("unroll")                                                 \
                for (int ni = 0; ni < 4; ni++) {                                  \
                    asm volatile(                                                 \
                        "mma.sync.aligned.m16n8k8.row.col.f32.tf32.tf32.f32 "     \
                        "{%0,%1,%2,%3}, {%4,%5,%6,%7}, {%8,%9}, {%0,%1,%2,%3};"   \
                        : "+f"(acc[mi][ni][0]), "+f"(acc[mi][ni][1]),             \
                          "+f"(acc[mi][ni][2]), "+f"(acc[mi][ni][3])              \
                        : "r"(af[mi][0]), "r"(af[mi][1]), "r"(af[mi][2]),         \
                          "r"(af[mi][3]), "r"(bf[ni][0]), "r"(bf[ni][1]));        \
                }                                                                 \
        }                                                                         \
    }

    LOAD_REGS(0)
    STORE_STAGE(0)
    __syncthreads();

    int s = 0;
    for (int k0 = GBK; k0 < Kd; k0 += GBK) {
        LOAD_REGS(k0)
        COMPUTE_STAGE(s)
        STORE_STAGE(s ^ 1)
        __syncthreads();
        s ^= 1;
    }
    COMPUTE_STAGE(s)

    // epilogue
#pragma unroll
    for (int mi = 0; mi < 4; mi++) {
#pragma unroll
        for (int ni = 0; ni < 4; ni++) {
            int row = blockIdx.y * GBM + wm * 64 + mi * 16 + fr;
            int col = blockIdx.x * GBN + wn * 32 + ni * 8 + fc * 2;
            float2 r0 = make_float2(acc[mi][ni][0], acc[mi][ni][1]);
            float2 r1 = make_float2(acc[mi][ni][2], acc[mi][ni][3]);
            if (res != nullptr) {
                float2 h0 = *(const float2*)(res + (size_t)row * N + col);
                float2 h1 = *(const float2*)(res + (size_t)(row + 8) * N + col);
                r0.x += h0.x; r0.y += h0.y;
                r1.x += h1.x; r1.y += h1.y;
            }
            *(float2*)(C + (size_t)row * N + col) = r0;
            *(float2*)(C + (size_t)(row + 8) * N + col) = r1;
        }
    }
}

// ---------------- silu(gate) * up ----------------
__global__ void silu_mul_k(float* __restrict__ gate, const float* __restrict__ up, int n) {
    int i = blockIdx.x * blockDim.x + threadIdx.x;
    if (i < n) {
        float gv = gate[i];
        float sig = 1.f / (1.f + __expf(-gv));
        gate[i] = gv * sig * up[i];
    }
}

// ---------------- launch ----------------
static void gemm(const float* A, const float* W, const float* res, float* C,
                 int M, int N, int Kd) {
    dim3 grid(N / GBN, M / GBM);
    tf32gemm_k<<<grid, 256>>>(A, W, res, C, M, N, Kd);
}

extern "C" void kernel_launch(void* const* d_in, const int* in_sizes, int n_in,
                              void* d_out, int out_size) {
    const float* hidden = (const float*)d_in[0];
    const float* sinp   = (const float*)d_in[1];
    const float* cosp   = (const float*)d_in[2];
    /* d_in[3] = mask (exact causal tril; applied analytically) */
    const float* ln1    = (const float*)d_in[4];
    const float* ln2    = (const float*)d_in[5];
    const float* qn     = (const float*)d_in[6];
    const float* kn     = (const float*)d_in[7];
    const float* q_w    = (const float*)d_in[8];
    const float* k_w    = (const float*)d_in[9];
    const float* v_w    = (const float*)d_in[10];
    const float* o_w    = (const float*)d_in[11];
    const float* gate_w = (const float*)d_in[12];
    const float* up_w   = (const float*)d_in[13];
    const float* down_w = (const float*)d_in[14];
    float* out = (float*)d_out;

    float *x, *q, *k, *v, *attn, *h2, *y, *gate, *up;
    cudaGetSymbolAddress((void**)&x, g_x);
    cudaGetSymbolAddress((void**)&q, g_q);
    cudaGetSymbolAddress((void**)&k, g_k);
    cudaGetSymbolAddress((void**)&v, g_v);
    cudaGetSymbolAddress((void**)&attn, g_attn);
    cudaGetSymbolAddress((void**)&h2, g_h2);
    cudaGetSymbolAddress((void**)&y, g_y);
    cudaGetSymbolAddress((void**)&gate, g_gate);
    cudaGetSymbolAddress((void**)&up, g_up);

    const int M = Mrows;

    rmsnorm_k<<<M, 256>>>(hidden, ln1, x);

    gemm(x, q_w, nullptr, q, M, Hn * Kn, Dn);
    gemm(x, k_w, nullptr, k, M, Gn * Kn, Dn);
    gemm(x, v_w, nullptr, v, M, Gn * Kn, Dn);

    {
        int warps_q = Bn * Tn * Hn;
        norm_rope_k<<<(warps_q * 32) / 256, 256>>>(q, qn, sinp, cosp, Hn);
        int warps_k = Bn * Tn * Gn;
        norm_rope_k<<<(warps_k * 32) / 256, 256>>>(k, kn, sinp, cosp, Gn);
    }

    {
        int warps = Bn * Tn * Gn;
        attn4_k<<<(warps * 32) / 256, 256>>>(q, k, v, attn);
    }

    gemm(attn, o_w, hidden, h2, M, Dn, Hn * Kn);

    rmsnorm_k<<<M, 256>>>(h2, ln2, y);

    gemm(y, gate_w, nullptr, gate, M, Fn, Dn);
    gemm(y, up_w, nullptr, up, M, Fn, Dn);

    {
        int n = M * Fn;
        silu_mul_k<<<(n + 255) / 256, 256>>>(gate, up, n);
    }

    gemm(gate, down_w, h2, out, M, Dn, Fn);
}

// round 4
// speedup vs baseline: 5.1550x; 2.9851x over previous
#include <cuda_runtime.h>
#include <math.h>
#include <stdint.h>

#define Bn 2
#define Tn 2048
#define Dn 1024
#define Hn 16
#define Gn 4
#define Kn 64
#define Rn (Hn / Gn)
#define Fn 4096
#define EPSF 1e-6f
#define Mrows (Bn * Tn)

// ---------------- scratch ----------------
__device__ float g_x[Mrows * Dn];
__device__ float g_q[Mrows * Hn * Kn];
__device__ float g_k[Mrows * Gn * Kn];
__device__ float g_v[Mrows * Gn * Kn];
__device__ float g_attn[Mrows * Hn * Kn];
__device__ float g_h2[Mrows * Dn];
__device__ float g_y[Mrows * Dn];
__device__ float g_gate[Mrows * Fn];
__device__ float g_up[Mrows * Fn];

// ---------------- helpers ----------------
__device__ __forceinline__ uint32_t tf32_bits(float x) {
    uint32_t u;
    asm("cvt.rna.tf32.f32 %0, %1;" : "=r"(u) : "f"(x));
    return u;
}
__device__ __forceinline__ float tf32_rna(float x) {
    return __uint_as_float(tf32_bits(x));
}
__device__ __forceinline__ uint32_t smem_u32(const void* p) {
    return (uint32_t)__cvta_generic_to_shared(p);
}
__device__ __forceinline__ void cpa16(uint32_t dst, const void* src) {
    asm volatile("cp.async.cg.shared.global [%0], [%1], 16;" ::"r"(dst), "l"(src));
}
#define CP_COMMIT asm volatile("cp.async.commit_group;")
#define CP_WAIT0 asm volatile("cp.async.wait_group 0;")
#define CP_WAIT1 asm volatile("cp.async.wait_group 1;")

#define MMA_TF32(d, a0, a1, a2, a3, b0, b1)                                   \
    asm volatile(                                                             \
        "mma.sync.aligned.m16n8k8.row.col.f32.tf32.tf32.f32 "                 \
        "{%0,%1,%2,%3}, {%4,%5,%6,%7}, {%8,%9}, {%0,%1,%2,%3};"               \
        : "+f"(d[0]), "+f"(d[1]), "+f"(d[2]), "+f"(d[3])                      \
        : "r"(a0), "r"(a1), "r"(a2), "r"(a3), "r"(b0), "r"(b1))

// ---------------- RMSNorm ----------------
__global__ void rmsnorm_k(const float* __restrict__ in, const float* __restrict__ sc,
                          float* __restrict__ out) {
    int row = blockIdx.x;
    const float* x = in + (size_t)row * Dn;
    float ss = 0.f;
    for (int i = threadIdx.x; i < Dn; i += blockDim.x) {
        float v = x[i];
        ss += v * v;
    }
    for (int o = 16; o; o >>= 1) ss += __shfl_xor_sync(0xFFFFFFFFu, ss, o);
    __shared__ float sm[8];
    int w = threadIdx.x >> 5;
    if ((threadIdx.x & 31) == 0) sm[w] = ss;
    __syncthreads();
    if (threadIdx.x == 0) {
        float tot = 0.f;
        for (int i = 0; i < 8; i++) tot += sm[i];
        sm[0] = tot;
    }
    __syncthreads();
    float inv = rsqrtf(sm[0] / (float)Dn + EPSF);
    float* o = out + (size_t)row * Dn;
    for (int i = threadIdx.x; i < Dn; i += blockDim.x) o[i] = x[i] * inv * sc[i];
}

// ---------------- per-head RMSNorm + RoPE ----------------
__global__ void norm_rope_k(float* __restrict__ qk, const float* __restrict__ nscale,
                            const float* __restrict__ sinp, const float* __restrict__ cosp,
                            int nheads) {
    int gw = (blockIdx.x * blockDim.x + threadIdx.x) >> 5;
    int lane = threadIdx.x & 31;
    int total = Bn * Tn * nheads;
    if (gw >= total) return;
    int bt = gw / nheads;
    float* p = qk + (size_t)gw * Kn;
    float x1 = p[lane];
    float x2 = p[lane + 32];
    float ss = x1 * x1 + x2 * x2;
    for (int o = 16; o; o >>= 1) ss += __shfl_xor_sync(0xFFFFFFFFu, ss, o);
    float inv = rsqrtf(ss / (float)Kn + EPSF);
    x1 = x1 * inv * nscale[lane];
    x2 = x2 * inv * nscale[lane + 32];
    float s = sinp[bt * (Kn / 2) + lane];
    float c = cosp[bt * (Kn / 2) + lane];
    p[lane]      = x1 * c - x2 * s;
    p[lane + 32] = x2 * c + x1 * s;
}

// ============================================================
// TF32 GEMM, cp.async 3-stage pipeline. 128x128x16 tile, 8 warps.
// ============================================================
#define GBM 128
#define GBN 128
#define GBK 16
#define SA 20
#define SB 136
#define GSTG 3
#define GEMM_SMEM ((GSTG * (GBM * SA + GBK * SB)) * 4)

struct GemmIdx {
    int a_row, a_col, b_row, b_col;
    int wm, wn, fr, fc;
};

__device__ __forceinline__ GemmIdx gemm_idx(int tid) {
    GemmIdx g;
    int lane = tid & 31, wid = tid >> 5;
    g.wm = wid >> 2; g.wn = wid & 3;
    g.fr = lane >> 2; g.fc = lane & 3;
    g.a_row = tid >> 2;        g.a_col = (tid & 3) * 4;
    g.b_row = tid >> 5;        g.b_col = (tid & 31) * 4;
    return g;
}

__device__ __forceinline__ void gemm_issue(const GemmIdx& gi, float* As, float* Bs, int stage,
                                           const float* Aptr, const float* Wptr,
                                           int k0, int N, int Kd) {
    uint32_t as = smem_u32(As + stage * GBM * SA);
    uint32_t bs = smem_u32(Bs + stage * GBK * SB);
    cpa16(as + (uint32_t)(gi.a_row * SA + gi.a_col) * 4,
          Aptr + (size_t)gi.a_row * Kd + k0 + gi.a_col);
    cpa16(as + (uint32_t)((gi.a_row + 64) * SA + gi.a_col) * 4,
          Aptr + (size_t)(gi.a_row + 64) * Kd + k0 + gi.a_col);
    cpa16(bs + (uint32_t)(gi.b_row * SB + gi.b_col) * 4,
          Wptr + (size_t)(k0 + gi.b_row) * N + gi.b_col);
    cpa16(bs + (uint32_t)((gi.b_row + 8) * SB + gi.b_col) * 4,
          Wptr + (size_t)(k0 + gi.b_row + 8) * N + gi.b_col);
}

__device__ __forceinline__ void gemm_compute(const GemmIdx& gi, const float* As, const float* Bs,
                                             int stage, float acc[4][4][4]) {
    const float* A = As + stage * GBM * SA;
    const float* B = Bs + stage * GBK * SB;
#pragma unroll
    for (int kk = 0; kk < GBK; kk += 8) {
        uint32_t af[4][4], bf[4][2];
#pragma unroll
        for (int mi = 0; mi < 4; mi++) {
            int r0 = gi.wm * 64 + mi * 16 + gi.fr;
            af[mi][0] = tf32_bits(A[r0 * SA + kk + gi.fc]);
            af[mi][1] = tf32_bits(A[(r0 + 8) * SA + kk + gi.fc]);
            af[mi][2] = tf32_bits(A[r0 * SA + kk + gi.fc + 4]);
            af[mi][3] = tf32_bits(A[(r0 + 8) * SA + kk + gi.fc + 4]);
        }
#pragma unroll
        for (int ni = 0; ni < 4; ni++) {
            int nc = gi.wn * 32 + ni * 8 + gi.fr;
            bf[ni][0] = tf32_bits(B[(kk + gi.fc) * SB + nc]);
            bf[ni][1] = tf32_bits(B[(kk + gi.fc + 4) * SB + nc]);
        }
#pragma unroll
        for (int mi = 0; mi < 4; mi++)
#pragma unroll
            for (int ni = 0; ni < 4; ni++)
                MMA_TF32(acc[mi][ni], af[mi][0], af[mi][1], af[mi][2], af[mi][3],
                         bf[ni][0], bf[ni][1]);
    }
}

__device__ __forceinline__ void gemm_body(const float* A, const float* W,
                                          const float* res, float* C,
                                          int M, int N, int Kd, int bx, int by,
                                          float* As, float* Bs) {
    GemmIdx gi = gemm_idx(threadIdx.x);
    const float* Aptr = A + (size_t)(by * GBM) * Kd;
    const float* Wptr = W + (size_t)bx * GBN;

    float acc[4][4][4];
#pragma unroll
    for (int mi = 0; mi < 4; mi++)
#pragma unroll
        for (int ni = 0; ni < 4; ni++)
#pragma unroll
            for (int c = 0; c < 4; c++) acc[mi][ni][c] = 0.f;

    int nk = Kd / GBK;
    gemm_issue(gi, As, Bs, 0, Aptr, Wptr, 0, N, Kd); CP_COMMIT;
    gemm_issue(gi, As, Bs, 1, Aptr, Wptr, GBK, N, Kd); CP_COMMIT;

    for (int i = 0; i < nk; i++) {
        CP_WAIT1;
        __syncthreads();
        if (i + 2 < nk) {
            gemm_issue(gi, As, Bs, (i + 2) % GSTG, Aptr, Wptr, (i + 2) * GBK, N, Kd);
            CP_COMMIT;
        }
        gemm_compute(gi, As, Bs, i % GSTG, acc);
        __syncthreads();
    }

#pragma unroll
    for (int mi = 0; mi < 4; mi++) {
#pragma unroll
        for (int ni = 0; ni < 4; ni++) {
            int row = by * GBM + gi.wm * 64 + mi * 16 + gi.fr;
            int col = bx * GBN + gi.wn * 32 + ni * 8 + gi.fc * 2;
            float2 r0 = make_float2(acc[mi][ni][0], acc[mi][ni][1]);
            float2 r1 = make_float2(acc[mi][ni][2], acc[mi][ni][3]);
            if (res != nullptr) {
                float2 h0 = *(const float2*)(res + (size_t)row * N + col);
                float2 h1 = *(const float2*)(res + (size_t)(row + 8) * N + col);
                r0.x += h0.x; r0.y += h0.y;
                r1.x += h1.x; r1.y += h1.y;
            }
            *(float2*)(C + (size_t)row * N + col) = r0;
            *(float2*)(C + (size_t)(row + 8) * N + col) = r1;
        }
    }
}

__global__ __launch_bounds__(256, 2) void tf32gemm_k(
    const float* __restrict__ A, const float* __restrict__ W,
    const float* __restrict__ res, float* __restrict__ C,
    int M, int N, int Kd) {
    extern __shared__ float smg[];
    float* As = smg;
    float* Bs = smg + GSTG * GBM * SA;
    gemm_body(A, W, res, C, M, N, Kd, blockIdx.x, blockIdx.y, As, Bs);
}

// fused q/k/v projection: bx 0..7 -> q (N=1024), 8..9 -> k, 10..11 -> v (N=256)
__global__ __launch_bounds__(256, 2) void tf32gemm_qkv_k(
    const float* __restrict__ A,
    const float* __restrict__ Wq, const float* __restrict__ Wk, const float* __restrict__ Wv,
    float* __restrict__ Cq, float* __restrict__ Ck, float* __restrict__ Cv) {
    extern __shared__ float smg[];
    float* As = smg;
    float* Bs = smg + GSTG * GBM * SA;
    int bx = blockIdx.x;
    const float* W; float* C; int N;
    if (bx < 8)       { W = Wq; C = Cq; N = 1024; }
    else if (bx < 10) { W = Wk; C = Ck; N = 256; bx -= 8; }
    else              { W = Wv; C = Cv; N = 256; bx -= 10; }
    gemm_body(A, W, nullptr, C, Mrows, N, Dn, bx, blockIdx.y, As, Bs);
}

// ============================================================
// Flash attention (tf32 mma), GQA-packed: M-tile = 32 t x 4 r = 128 rows.
// Each warp owns 16 COMPLETE rows (all 128 key cols) -> softmax stats
// never cross warps; P is warp-private in smem.
// ============================================================
#define QSS 68
#define KSS 68
#define VSS 72
#define PSS 132
#define ATT_SMEM ((128 * QSS + 128 * KSS + 128 * VSS + 128 * PSS) * 4)

__global__ __launch_bounds__(256, 1) void flashattn_k(
    const float* __restrict__ q, const float* __restrict__ k,
    const float* __restrict__ v, float* __restrict__ out) {
    extern __shared__ float sm[];
    float* Qs = sm;
    float* Ks = Qs + 128 * QSS;
    float* Vs = Ks + 128 * KSS;
    float* Ps = Vs + 128 * VSS;
    uint32_t qs_u = smem_u32(Qs), ks_u = smem_u32(Ks), vs_u = smem_u32(Vs);

    int tid = threadIdx.x;
    int lane = tid & 31, wid = tid >> 5;
    int fr = lane >> 2, fc = lane & 3;
    float* Pw = Ps + wid * 16 * PSS;  // warp-private 16 rows

    int bg = blockIdx.y;
    int b = bg >> 2, g = bg & 3;
    int t0 = (gridDim.x - 1 - blockIdx.x) * 32;  // longest blocks first
    int ntiles = (t0 >> 7) + 1;

    const float* qbase = q + ((size_t)((size_t)b * Tn + t0) * Hn + g * Rn) * Kn;
    const float* kbase = k + ((size_t)b * Tn * Gn + g) * Kn;
    const float* vbase = v + ((size_t)b * Tn * Gn + g) * Kn;

    // load Q tile (rows m: t=t0+(m>>2), r=m&3)
#pragma unroll
    for (int i = 0; i < 8; i++) {
        int idx = tid + (i << 8);
        int m = idx >> 4, c4 = (idx & 15) << 2;
        cpa16(qs_u + (uint32_t)(m * QSS + c4) * 4,
              qbase + (size_t)(m >> 2) * (Hn * Kn) + (m & 3) * Kn + c4);
    }
    CP_COMMIT;
#pragma unroll
    for (int i = 0; i < 8; i++) {
        int idx = tid + (i << 8);
        int j = idx >> 4, c4 = (idx & 15) << 2;
        cpa16(ks_u + (uint32_t)(j * KSS + c4) * 4, kbase + (size_t)j * (Gn * Kn) + c4);
    }
    CP_COMMIT;
#pragma unroll
    for (int i = 0; i < 8; i++) {
        int idx = tid + (i << 8);
        int j = idx >> 4, c4 = (idx & 15) << 2;
        cpa16(vs_u + (uint32_t)(j * VSS + c4) * 4, vbase + (size_t)j * (Gn * Kn) + c4);
    }
    CP_COMMIT;
    CP_WAIT0;
    __syncthreads();

    float m_r[2], l_r[2], acco[8][4];
#pragma unroll
    for (int h = 0; h < 2; h++) { m_r[h] = -INFINITY; l_r[h] = 0.f; }
#pragma unroll
    for (int ni = 0; ni < 8; ni++)
#pragma unroll
        for (int c = 0; c < 4; c++) acco[ni][c] = 0.f;

    int r0 = wid * 16 + fr;  // this thread's base S row (and r0+8)

    for (int it = 0; it < ntiles; it++) {
        int s0 = it << 7;
        bool more = (it + 1 < ntiles);

        // ---- S = Q @ K^T : 16 rows x 128 cols per warp ----
        float accs[16][4];
#pragma unroll
        for (int ni = 0; ni < 16; ni++)
#pragma unroll
            for (int c = 0; c < 4; c++) accs[ni][c] = 0.f;

#pragma unroll
        for (int kc = 0; kc < 64; kc += 8) {
            uint32_t af[4];
            af[0] = tf32_bits(Qs[r0 * QSS + kc + fc]);
            af[1] = tf32_bits(Qs[(r0 + 8) * QSS + kc + fc]);
            af[2] = tf32_bits(Qs[r0 * QSS + kc + fc + 4]);
            af[3] = tf32_bits(Qs[(r0 + 8) * QSS + kc + fc + 4]);
#pragma unroll
            for (int ni = 0; ni < 16; ni++) {
                int nc = ni * 8 + fr;
                uint32_t b0 = tf32_bits(Ks[nc * KSS + kc + fc]);
                uint32_t b1 = tf32_bits(Ks[nc * KSS + kc + fc + 4]);
                MMA_TF32(accs[ni], af[0], af[1], af[2], af[3], b0, b1);
            }
        }

        // scale + causal mask (only last tile can cross the diagonal)
#pragma unroll
        for (int ni = 0; ni < 16; ni++)
#pragma unroll
            for (int c = 0; c < 4; c++) accs[ni][c] *= 0.125f;
        if (it == ntiles - 1) {
#pragma unroll
            for (int ni = 0; ni < 16; ni++)
#pragma unroll
                for (int c = 0; c < 4; c++) {
                    int row = r0 + ((c >= 2) ? 8 : 0);
                    int tt = t0 + (row >> 2);
                    int ss = s0 + ni * 8 + fc * 2 + (c & 1);
                    if (ss > tt) accs[ni][c] = -1e30f;
                }
        }

        // ---- online softmax: rows fully owned by this warp ----
#pragma unroll
        for (int h = 0; h < 2; h++) {
            float mx = -1e30f;
#pragma unroll
            for (int ni = 0; ni < 16; ni++) {
                mx = fmaxf(mx, accs[ni][2 * h]);
                mx = fmaxf(mx, accs[ni][2 * h + 1]);
            }
            mx = fmaxf(mx, __shfl_xor_sync(0xFFFFFFFFu, mx, 1));
            mx = fmaxf(mx, __shfl_xor_sync(0xFFFFFFFFu, mx, 2));
            float mnew = fmaxf(m_r[h], mx);
            float corr = __expf(m_r[h] - mnew);
            m_r[h] = mnew;
            float sum = 0.f;
#pragma unroll
            for (int ni = 0; ni < 16; ni++) {
                float p0 = __expf(accs[ni][2 * h] - mnew);
                float p1 = __expf(accs[ni][2 * h + 1] - mnew);
                accs[ni][2 * h] = p0;
                accs[ni][2 * h + 1] = p1;
                sum += p0 + p1;
            }
            sum += __shfl_xor_sync(0xFFFFFFFFu, sum, 1);
            sum += __shfl_xor_sync(0xFFFFFFFFu, sum, 2);
            l_r[h] = l_r[h] * corr + sum;
#pragma unroll
            for (int ni = 0; ni < 8; ni++) {
                acco[ni][2 * h] *= corr;
                acco[ni][2 * h + 1] *= corr;
            }
        }

        // ---- P -> warp-private smem (tf32-converted) ----
#pragma unroll
        for (int ni = 0; ni < 16; ni++) {
            int cc = ni * 8 + fc * 2;
            *(float2*)(Pw + fr * PSS + cc) =
                make_float2(tf32_rna(accs[ni][0]), tf32_rna(accs[ni][1]));
            *(float2*)(Pw + (fr + 8) * PSS + cc) =
                make_float2(tf32_rna(accs[ni][2]), tf32_rna(accs[ni][3]));
        }

        __syncthreads();  // all warps done reading Ks
        if (more) {
            int sn = s0 + 128;
#pragma unroll
            for (int i = 0; i < 8; i++) {
                int idx = tid + (i << 8);
                int j = idx >> 4, c4 = (idx & 15) << 2;
                cpa16(ks_u + (uint32_t)(j * KSS + c4) * 4,
                      kbase + (size_t)(sn + j) * (Gn * Kn) + c4);
            }
            CP_COMMIT;
            CP_WAIT1;  // V(it) complete
        } else {
            CP_WAIT0;
        }
        __syncthreads();

        // ---- O += P @ V : 16 rows x 64 cols per warp ----
#pragma unroll
        for (int kc = 0; kc < 128; kc += 8) {
            uint32_t af[4];
            af[0] = __float_as_uint(Pw[fr * PSS + kc + fc]);
            af[1] = __float_as_uint(Pw[(fr + 8) * PSS + kc + fc]);
            af[2] = __float_as_uint(Pw[fr * PSS + kc + fc + 4]);
            af[3] = __float_as_uint(Pw[(fr + 8) * PSS + kc + fc + 4]);
#pragma unroll
            for (int ni = 0; ni < 8; ni++) {
                int n0 = ni * 8 + fr;
                uint32_t b0 = tf32_bits(Vs[(kc + fc) * VSS + n0]);
                uint32_t b1 = tf32_bits(Vs[(kc + fc + 4) * VSS + n0]);
                MMA_TF32(acco[ni], af[0], af[1], af[2], af[3], b0, b1);
            }
        }
        __syncthreads();  // all warps done reading Vs

        if (more) {
            int sn = s0 + 128;
#pragma unroll
            for (int i = 0; i < 8; i++) {
                int idx = tid + (i << 8);
                int j = idx >> 4, c4 = (idx & 15) << 2;
                cpa16(vs_u + (uint32_t)(j * VSS + c4) * 4,
                      vbase + (size_t)(sn + j) * (Gn * Kn) + c4);
            }
            CP_COMMIT;
            CP_WAIT1;  // K(it+1) complete
            __syncthreads();
        }
    }

    // ---- epilogue: O / l ----
#pragma unroll
    for (int h = 0; h < 2; h++) {
        float inv = 1.f / l_r[h];
        int row = r0 + 8 * h;
        int tt = t0 + (row >> 2);
        int hh = g * Rn + (row & 3);
        float* op = out + ((size_t)((size_t)b * Tn + tt) * Hn + hh) * Kn;
#pragma unroll
        for (int ni = 0; ni < 8; ni++) {
            int col = ni * 8 + fc * 2;
            *(float2*)(op + col) =
                make_float2(acco[ni][2 * h] * inv, acco[ni][2 * h + 1] * inv);
        }
    }
}

// ---------------- silu(gate) * up ----------------
__global__ void silu_mul_k(float* __restrict__ gate, const float* __restrict__ up, int n4) {
    int i = blockIdx.x * blockDim.x + threadIdx.x;
    if (i < n4) {
        float4 gv = ((float4*)gate)[i];
        float4 uv = ((const float4*)up)[i];
        gv.x = gv.x / (1.f + __expf(-gv.x)) * uv.x;
        gv.y = gv.y / (1.f + __expf(-gv.y)) * uv.y;
        gv.z = gv.z / (1.f + __expf(-gv.z)) * uv.z;
        gv.w = gv.w / (1.f + __expf(-gv.w)) * uv.w;
        ((float4*)gate)[i] = gv;
    }
}

// ---------------- launch ----------------
static void gemm(const float* A, const float* W, const float* res, float* C,
                 int M, int N, int Kd) {
    dim3 grid(N / GBN, M / GBM);
    tf32gemm_k<<<grid, 256, GEMM_SMEM>>>(A, W, res, C, M, N, Kd);
}

extern "C" void kernel_launch(void* const* d_in, const int* in_sizes, int n_in,
                              void* d_out, int out_size) {
    const float* hidden = (const float*)d_in[0];
    const float* sinp   = (const float*)d_in[1];
    const float* cosp   = (const float*)d_in[2];
    /* d_in[3] = mask (exact causal tril; applied analytically) */
    const float* ln1    = (const float*)d_in[4];
    const float* ln2    = (const float*)d_in[5];
    const float* qn     = (const float*)d_in[6];
    const float* kn     = (const float*)d_in[7];
    const float* q_w    = (const float*)d_in[8];
    const float* k_w    = (const float*)d_in[9];
    const float* v_w    = (const float*)d_in[10];
    const float* o_w    = (const float*)d_in[11];
    const float* gate_w = (const float*)d_in[12];
    const float* up_w   = (const float*)d_in[13];
    const float* down_w = (const float*)d_in[14];
    float* out = (float*)d_out;

    cudaFuncSetAttribute(tf32gemm_k, cudaFuncAttributeMaxDynamicSharedMemorySize, GEMM_SMEM);
    cudaFuncSetAttribute(tf32gemm_qkv_k, cudaFuncAttributeMaxDynamicSharedMemorySize, GEMM_SMEM);
    cudaFuncSetAttribute(flashattn_k, cudaFuncAttributeMaxDynamicSharedMemorySize, ATT_SMEM);

    float *x, *q, *k, *v, *attn, *h2, *y, *gate, *up;
    cudaGetSymbolAddress((void**)&x, g_x);
    cudaGetSymbolAddress((void**)&q, g_q);
    cudaGetSymbolAddress((void**)&k, g_k);
    cudaGetSymbolAddress((void**)&v, g_v);
    cudaGetSymbolAddress((void**)&attn, g_attn);
    cudaGetSymbolAddress((void**)&h2, g_h2);
    cudaGetSymbolAddress((void**)&y, g_y);
    cudaGetSymbolAddress((void**)&gate, g_gate);
    cudaGetSymbolAddress((void**)&up, g_up);

    const int M = Mrows;

    rmsnorm_k<<<M, 256>>>(hidden, ln1, x);

    tf32gemm_qkv_k<<<dim3(12, M / GBM), 256, GEMM_SMEM>>>(x, q_w, k_w, v_w, q, k, v);

    {
        int warps_q = Bn * Tn * Hn;
        norm_rope_k<<<(warps_q * 32) / 256, 256>>>(q, qn, sinp, cosp, Hn);
        int warps_k = Bn * Tn * Gn;
        norm_rope_k<<<(warps_k * 32) / 256, 256>>>(k, kn, sinp, cosp, Gn);
    }

    flashattn_k<<<dim3(Tn / 32, Bn * Gn), 256, ATT_SMEM>>>(q, k, v, attn);

    gemm(attn, o_w, hidden, h2, M, Dn, Hn * Kn);

    rmsnorm_k<<<M, 256>>>(h2, ln2, y);

    gemm(y, gate_w, nullptr, gate, M, Fn, Dn);
    gemm(y, up_w, nullptr, up, M, Fn, Dn);

    {
        int n4 = M * Fn / 4;
        silu_mul_k<<<(n4 + 255) / 256, 256>>>(gate, up, n4);
    }

    gemm(gate, down_w, h2, out, M, Dn, Fn);
}